// round 2
// baseline (speedup 1.0000x reference)
#include <cuda_runtime.h>

// Problem constants (match reference: D=48, K=12, S=4, BS=8)
#define D_   48
#define N_   (D_ * D_)      // 2304
#define K_   12
#define KK_  (K_ * K_)      // 144
#define NW1_ 10             // windows per dim: (48-12)/4 + 1
#define NW_  (NW1_ * NW1_)  // 100
#define BS_  8

// out[b, w, i, j] = x[b, idx[w,i], idx[w,j]]
// idx[w, p] = (wr*4 + pa)*48 + (wc*4 + pb), w=(wr,wc), p=(pa,pb)
//
// One thread handles one 12-float contiguous chunk of the j dimension
// (fixed b,w,i,ja; jb = 0..11). Source chunk starts at column
// (wr*4+ja)*48 + wc*4  -> multiple of 4 floats -> 16B aligned.
// Dest chunk is at linear float offset t*12 -> also 16B aligned.
__global__ void __launch_bounds__(256) submanifold_gather(
    const float* __restrict__ x, float* __restrict__ out)
{
    int t = blockIdx.x * 256 + threadIdx.x;
    // total = BS_*NW_*KK_*K_ = 1,382,400 ; grid sized exactly, no bounds check needed
    int ja   = t % K_;
    int rest = t / K_;
    int i    = rest % KK_;
    rest     = rest / KK_;
    int w    = rest % NW_;
    int b    = rest / NW_;

    int wr = w / NW1_;
    int wc = w % NW1_;
    int ia = i / K_;
    int ib = i % K_;

    int r = (wr * 4 + ia) * D_ + wc * 4 + ib;   // source row (token index)
    int c = (wr * 4 + ja) * D_ + wc * 4;        // source col chunk base (16B aligned)

    const float4* __restrict__ src =
        reinterpret_cast<const float4*>(x + ((size_t)b * N_ + r) * N_ + c);
    float4* __restrict__ dst =
        reinterpret_cast<float4*>(out + (size_t)t * K_);

    float4 v0 = src[0];
    float4 v1 = src[1];
    float4 v2 = src[2];
    dst[0] = v0;
    dst[1] = v1;
    dst[2] = v2;
}

extern "C" void kernel_launch(void* const* d_in, const int* in_sizes, int n_in,
                              void* d_out, int out_size)
{
    const float* x = (const float*)d_in[0];
    float* out = (float*)d_out;

    const int total  = BS_ * NW_ * KK_ * K_;   // 1,382,400
    const int blocks = total / 256;            // 5400 exactly
    submanifold_gather<<<blocks, 256>>>(x, out);
}

// round 3
// speedup vs baseline: 1.1691x; 1.1691x over previous
#include <cuda_runtime.h>

// Problem constants (match reference: D=48, K=12, S=4, BS=8)
#define D_   48
#define N_   (D_ * D_)      // 2304
#define K_   12
#define KK_  (K_ * K_)      // 144
#define NW1_ 10             // (48-12)/4 + 1
#define NW_  (NW1_ * NW1_)  // 100
#define BS_  8
#define QPR_ 36             // float4 quads per output row (144 floats / 4)

// out[b, w, i, j] = x[b, idx[w,i], idx[w,j]]
// idx[w, p] = (wr*4 + pa)*48 + (wc*4 + pb)
//
// One thread = one 16B quad of the output, in exact output linear order.
// Quad q (0..35) within row (b,w,i): ja = q/3, sub = q%3.
// Source address: row r = (wr*4+ia)*48 + wc*4 + ib,
//                 col c = (wr*4+ja)*48 + wc*4 + sub*4   (16B aligned).
// A warp covers 32 consecutive quads -> the 12 runs of a source row are
// read with adjacent lanes sharing cache lines (each line touched once),
// and stores are 512B fully coalesced.
__global__ void __launch_bounds__(256) submanifold_gather_q(
    const float* __restrict__ x, float* __restrict__ out)
{
    int t = blockIdx.x * 256 + threadIdx.x;   // quad id; grid sized exactly
    int q    = t % QPR_;
    int rest = t / QPR_;
    int i    = rest % KK_;
    rest     = rest / KK_;
    int w    = rest % NW_;
    int b    = rest / NW_;

    int wr = w / NW1_;
    int wc = w % NW1_;
    int ia = i / K_;
    int ib = i % K_;
    int ja  = q / 3;
    int sub = q % 3;

    int r = (wr * 4 + ia) * D_ + wc * 4 + ib;          // source row token
    int c = (wr * 4 + ja) * D_ + wc * 4 + sub * 4;     // source col (16B aligned)

    const float4* __restrict__ src =
        reinterpret_cast<const float4*>(x + ((size_t)b * N_ + r) * N_ + c);
    float4* __restrict__ dst = reinterpret_cast<float4*>(out) + t;

    *dst = *src;
}

extern "C" void kernel_launch(void* const* d_in, const int* in_sizes, int n_in,
                              void* d_out, int out_size)
{
    const float* x = (const float*)d_in[0];
    float* out = (float*)d_out;

    const int total_quads = BS_ * NW_ * KK_ * QPR_;   // 4,147,200
    const int blocks = total_quads / 256;             // 16,200 exactly
    submanifold_gather_q<<<blocks, 256>>>(x, out);
}

// round 4
// speedup vs baseline: 1.2745x; 1.0902x over previous
#include <cuda_runtime.h>

// Problem constants (match reference: D=48, K=12, S=4, BS=8)
#define D_   48
#define N_   (D_ * D_)      // 2304
#define K_   12
#define KK_  (K_ * K_)      // 144
#define NW1_ 10             // (48-12)/4 + 1
#define NW_  (NW1_ * NW1_)  // 100
#define BS_  8
#define QPR_ 36             // float4 quads per output row (144 floats / 4)

// out[b, w, i, j] = x[b, idx[w,i], idx[w,j]]
// idx[w, p] = (wr*4 + pa)*48 + (wc*4 + pb)
//
// One thread moves FOUR 16B quads: same quad q of 4 consecutive output rows
// i = ia*12 + ib4*4 + {0,1,2,3}. The 4 source addresses are the same column
// in 4 consecutive source token rows (stride N_=2304 floats) -> one index
// computation, 4 independent LDG.128 (MLP=4). q=0..35 runs fastest across
// threads, so each of the 4 stores is a fully-coalesced warp store, and a
// warp's loads touch each source-row cache line once.
__global__ void __launch_bounds__(256) submanifold_gather_q4(
    const float* __restrict__ x, float* __restrict__ out)
{
    int t = blockIdx.x * 256 + threadIdx.x;   // grid sized exactly
    int q    = t % QPR_;
    int rest = t / QPR_;
    int ib4  = rest % 3;          // which group of 4 within ib (0..2)
    rest     = rest / 3;
    int ia   = rest % K_;
    rest     = rest / K_;
    int w    = rest % NW_;
    int b    = rest / NW_;

    int wr = w / NW1_;
    int wc = w % NW1_;
    int ja  = q / 3;
    int sub = q % 3;

    // source: row r0..r0+3, fixed col c
    int r0 = (wr * 4 + ia) * D_ + wc * 4 + ib4 * 4;
    int c  = (wr * 4 + ja) * D_ + wc * 4 + sub * 4;   // 16B aligned

    const float4* __restrict__ src =
        reinterpret_cast<const float4*>(x + ((size_t)b * N_ + r0) * N_ + c);

    // dest: quad q of output rows i0..i0+3
    int i0 = ia * K_ + ib4 * 4;
    size_t dbase = (((size_t)(b * NW_ + w)) * KK_ + i0) * QPR_ + q;
    float4* __restrict__ dst = reinterpret_cast<float4*>(out) + dbase;

    float4 v0 = src[0 * (N_ / 4)];
    float4 v1 = src[1 * (N_ / 4)];
    float4 v2 = src[2 * (N_ / 4)];
    float4 v3 = src[3 * (N_ / 4)];

    dst[0 * QPR_] = v0;
    dst[1 * QPR_] = v1;
    dst[2 * QPR_] = v2;
    dst[3 * QPR_] = v3;
}

extern "C" void kernel_launch(void* const* d_in, const int* in_sizes, int n_in,
                              void* d_out, int out_size)
{
    const float* x = (const float*)d_in[0];
    float* out = (float*)d_out;

    const int total_threads = BS_ * NW_ * KK_ * QPR_ / 4;  // 1,036,800
    const int blocks = total_threads / 256;                // 4050 exactly
    submanifold_gather_q4<<<blocks, 256>>>(x, out);
}

// round 5
// speedup vs baseline: 1.4381x; 1.1283x over previous
#include <cuda_runtime.h>

// Problem constants (match reference: D=48, K=12, S=4, BS=8)
#define D_   48
#define N_   (D_ * D_)      // 2304
#define K_   12
#define KK_  (K_ * K_)      // 144
#define NW1_ 10             // (48-12)/4 + 1
#define NW_  (NW1_ * NW1_)  // 100
#define BS_  8
#define QPR_ 36             // float4 quads per output row (144 floats / 4)

// out[b, w, i=(ia,ib), j=(ja,jb)] = x[b, R0+ib, C0+jb]
//   R0 = (wr*4+ia)*48 + wc*4,  C0 = (wr*4+ja)*48 + wc*4
// i.e. each (b,w,ia,ja) output tile is a CONTIGUOUS 12x12 submatrix of x.
//
// One thread = one column quad q (ja,sub) for ALL 12 ib rows:
//   - one index computation
//   - 12 independent LDG.128 (row stride 2304 floats) -> MLP=12
//   - 12 streaming stores (__stcs) so the write-once output doesn't evict
//     the heavily-reused x from L2.
__global__ void __launch_bounds__(256) submanifold_gather_q12(
    const float* __restrict__ x, float* __restrict__ out)
{
    int t = blockIdx.x * 256 + threadIdx.x;   // grid sized exactly
    int q    = t % QPR_;
    int rest = t / QPR_;
    int ia   = rest % K_;
    rest     = rest / K_;
    int w    = rest % NW_;
    int b    = rest / NW_;

    int wr = w / NW1_;
    int wc = w % NW1_;
    int ja  = q / 3;
    int sub = q % 3;

    int r0 = (wr * 4 + ia) * D_ + wc * 4;             // first of 12 source rows
    int c  = (wr * 4 + ja) * D_ + wc * 4 + sub * 4;   // 16B-aligned column

    const float4* __restrict__ src =
        reinterpret_cast<const float4*>(x + ((size_t)b * N_ + r0) * N_ + c);

    // dest: quad q of output rows i = ia*12 + ib, ib = 0..11
    size_t dbase = (((size_t)(b * NW_ + w)) * KK_ + ia * K_) * QPR_ + q;
    float4* __restrict__ dst = reinterpret_cast<float4*>(out) + dbase;

    float4 v[K_];
#pragma unroll
    for (int ib = 0; ib < K_; ib++)
        v[ib] = src[(size_t)ib * (N_ / 4)];

#pragma unroll
    for (int ib = 0; ib < K_; ib++)
        __stcs(&dst[(size_t)ib * QPR_], v[ib]);
}

extern "C" void kernel_launch(void* const* d_in, const int* in_sizes, int n_in,
                              void* d_out, int out_size)
{
    const float* x = (const float*)d_in[0];
    float* out = (float*)d_out;

    const int total_threads = BS_ * NW_ * K_ * QPR_;   // 345,600
    const int blocks = total_threads / 256;            // 1350 exactly
    submanifold_gather_q12<<<blocks, 256>>>(x, out);
}